// round 9
// baseline (speedup 1.0000x reference)
#include <cuda_runtime.h>
#include <cuda_bf16.h>
#include <cuda_fp16.h>
#include <cstdint>

#define BB 16
#define LL 1024
#define FF 512
#define HH 8
#define DD 64

// fp32 intermediates
__device__ float g_q[BB*HH*LL*DD];
__device__ float g_kT[BB*HH*DD*LL];
// preconverted inputs / weights (bf16 hi/lo packed as uint32 pairs)
__device__ uint32_t g_iqh[16384*256], g_iql[16384*256];
__device__ uint32_t g_ikh[16384*256], g_ikl[16384*256];
__device__ uint32_t g_wh[4][512*256], g_wl[4][512*256];
// V fp16 hi/lo packed, layout (b,h,l,d/2)
__device__ uint32_t g_vh[BB*HH*LL*32], g_vl[BB*HH*LL*32];
// attn output bf16 hi/lo packed, row-major [16384][256]
__device__ uint32_t g_xh[16384*256], g_xl[16384*256];

// ===========================================================================
// helpers
// ===========================================================================
__device__ __forceinline__ uint32_t s2u(const void* p) {
    return (uint32_t)__cvta_generic_to_shared(p);
}
__device__ __forceinline__ void ldsm4(uint32_t* r, uint32_t a) {
    asm volatile("ldmatrix.sync.aligned.m8n8.x4.shared.b16 {%0,%1,%2,%3}, [%4];"
                 : "=r"(r[0]), "=r"(r[1]), "=r"(r[2]), "=r"(r[3]) : "r"(a));
}
__device__ __forceinline__ void ldsm4t(uint32_t* r, uint32_t a) {
    asm volatile("ldmatrix.sync.aligned.m8n8.x4.trans.shared.b16 {%0,%1,%2,%3}, [%4];"
                 : "=r"(r[0]), "=r"(r[1]), "=r"(r[2]), "=r"(r[3]) : "r"(a));
}
__device__ __forceinline__ void mma_bf16(float* c, const uint32_t* a, const uint32_t* b) {
    asm volatile(
        "mma.sync.aligned.m16n8k16.row.col.f32.bf16.bf16.f32 "
        "{%0,%1,%2,%3}, {%4,%5,%6,%7}, {%8,%9}, {%0,%1,%2,%3};"
        : "+f"(c[0]), "+f"(c[1]), "+f"(c[2]), "+f"(c[3])
        : "r"(a[0]), "r"(a[1]), "r"(a[2]), "r"(a[3]), "r"(b[0]), "r"(b[1]));
}
__device__ __forceinline__ void mma_f16(float* c, const uint32_t* a, const uint32_t* b) {
    asm volatile(
        "mma.sync.aligned.m16n8k16.row.col.f32.f16.f16.f32 "
        "{%0,%1,%2,%3}, {%4,%5,%6,%7}, {%8,%9}, {%0,%1,%2,%3};"
        : "+f"(c[0]), "+f"(c[1]), "+f"(c[2]), "+f"(c[3])
        : "r"(a[0]), "r"(a[1]), "r"(a[2]), "r"(a[3]), "r"(b[0]), "r"(b[1]));
}
__device__ __forceinline__ uint32_t packbf(float a, float b) {
    uint32_t r;
    asm("cvt.rn.bf16x2.f32 %0, %1, %2;" : "=r"(r) : "f"(b), "f"(a));
    return r;
}
__device__ __forceinline__ uint32_t packhf(float a, float b) {
    __half2 h = __floats2half2_rn(a, b);
    return *(uint32_t*)&h;
}
__device__ __forceinline__ void cpa16(uint32_t dst, const void* src) {
    asm volatile("cp.async.cg.shared.global [%0], [%1], 16;" :: "r"(dst), "l"(src));
}
__device__ __forceinline__ void cpa_commit() {
    asm volatile("cp.async.commit_group;" ::: "memory");
}
template<int N> __device__ __forceinline__ void cpa_wait() {
    asm volatile("cp.async.wait_group %0;" :: "n"(N) : "memory");
}

// ===========================================================================
// fp32 -> bf16 hi/lo split conversion (elementwise)
// ===========================================================================
__global__ void conv_split(const float4* __restrict__ in,
                           uint32_t* __restrict__ hi, uint32_t* __restrict__ lo, int n4)
{
    int i = blockIdx.x * blockDim.x + threadIdx.x;
    if (i >= n4) return;
    float4 v = in[i];
    uint32_t h0 = packbf(v.x, v.y), h1 = packbf(v.z, v.w);
    float rx = v.x - __uint_as_float(h0 << 16);
    float ry = v.y - __uint_as_float(h0 & 0xFFFF0000u);
    float rz = v.z - __uint_as_float(h1 << 16);
    float rw = v.w - __uint_as_float(h1 & 0xFFFF0000u);
    hi[2 * i] = h0; hi[2 * i + 1] = h1;
    lo[2 * i] = packbf(rx, ry); lo[2 * i + 1] = packbf(rz, rw);
}

// ===========================================================================
// Split-bf16 GEMM on preconverted operands, cp.async 2-stage pipeline.
// C = A(16384,512) @ W(512,512) + bias. CTA 128x128, 8 warps, warp 64x32.
// mode 0: fp32 row-major; 1: fp32 scatter (B,H,L,D); 2: fp32 scatter (B,H,D,L);
// mode 3: fp16 hi/lo packed scatter (b,h,l,d/2) into Ch/Cl.
// ===========================================================================
#define SA 40
#define SB 136
#define GB_SMEM (18944 * 4)

__global__ void __launch_bounds__(256) gemm_bf(
    const uint32_t* __restrict__ Ah, const uint32_t* __restrict__ Al,
    const uint32_t* __restrict__ Wh, const uint32_t* __restrict__ Wl,
    const float* __restrict__ bias, float* __restrict__ Cf,
    uint32_t* __restrict__ Ch, uint32_t* __restrict__ Cl, int mode)
{
    extern __shared__ uint32_t su[];
    uint32_t* sAh[2] = { su,         su + 2560 };
    uint32_t* sAl[2] = { su + 5120,  su + 7680 };
    uint32_t* sBh[2] = { su + 10240, su + 12416 };
    uint32_t* sBl[2] = { su + 14592, su + 16768 };

    const int t    = threadIdx.x;
    const int warp = t >> 5;
    const int lane = t & 31;
    const int bm   = blockIdx.y * 128;
    const int bnu  = blockIdx.x * 64;        // uint32 col offset
    const int wm   = (warp >> 2) * 64;
    const int wn   = (warp & 3) * 32;

    auto prefetch = [&](int c, int p) {
        const int k0h = c * 16;              // k-chunk offset in uint32
        #pragma unroll
        for (int j = 0; j < 2; j++) {
            int id = t + 256 * j;
            int row = id >> 2, seg = (id & 3) * 4;
            size_t g = (size_t)(bm + row) * 256 + k0h + seg;
            int so = row * 20 + seg;
            cpa16(s2u(sAh[p] + so), Ah + g);
            cpa16(s2u(sAl[p] + so), Al + g);
        }
        #pragma unroll
        for (int j = 0; j < 2; j++) {
            int id = t + 256 * j;
            int row = id >> 4, seg = (id & 15) * 4;
            size_t g = (size_t)(c * 32 + row) * 256 + bnu + seg;
            int so = row * 68 + seg;
            cpa16(s2u(sBh[p] + so), Wh + g);
            cpa16(s2u(sBl[p] + so), Wl + g);
        }
    };

    float acc[4][4][4];
    #pragma unroll
    for (int mt = 0; mt < 4; mt++)
        #pragma unroll
        for (int nt = 0; nt < 4; nt++)
            #pragma unroll
            for (int i = 0; i < 4; i++) acc[mt][nt][i] = 0.f;

    prefetch(0, 0); cpa_commit();

    for (int c = 0; c < 16; c++) {
        const int p = c & 1;
        if (c + 1 < 16) { prefetch(c + 1, (c + 1) & 1); cpa_commit(); cpa_wait<1>(); }
        else            { cpa_wait<0>(); }
        __syncthreads();

        const char* pAh = (const char*)sAh[p];
        const char* pAl = (const char*)sAl[p];
        const char* pBh = (const char*)sBh[p];
        const char* pBl = (const char*)sBl[p];

        #pragma unroll
        for (int ks = 0; ks < 2; ks++) {
            const int kk = ks * 16;
            uint32_t ah[4][4], al[4][4];
            {
                int arow = (lane & 15);
                int acol = kk + ((lane >> 4) << 3);
                #pragma unroll
                for (int mt = 0; mt < 4; mt++) {
                    int boff = ((wm + mt * 16 + arow) * SA + acol) * 2;
                    ldsm4(ah[mt], s2u(pAh + boff));
                    ldsm4(al[mt], s2u(pAl + boff));
                }
            }
            uint32_t bh[4][2], bl[4][2];
            {
                int brow = kk + (lane & 15);
                int bcol = ((lane >> 4) << 3);
                #pragma unroll
                for (int ntp = 0; ntp < 2; ntp++) {
                    int boff = (brow * SB + wn + ntp * 16 + bcol) * 2;
                    uint32_t tmp[4];
                    ldsm4t(tmp, s2u(pBh + boff));
                    bh[ntp * 2][0] = tmp[0]; bh[ntp * 2][1] = tmp[1];
                    bh[ntp * 2 + 1][0] = tmp[2]; bh[ntp * 2 + 1][1] = tmp[3];
                    ldsm4t(tmp, s2u(pBl + boff));
                    bl[ntp * 2][0] = tmp[0]; bl[ntp * 2][1] = tmp[1];
                    bl[ntp * 2 + 1][0] = tmp[2]; bl[ntp * 2 + 1][1] = tmp[3];
                }
            }
            #pragma unroll
            for (int mt = 0; mt < 4; mt++)
                #pragma unroll
                for (int nt = 0; nt < 4; nt++) {
                    mma_bf16(acc[mt][nt], ah[mt], bh[nt]);
                    mma_bf16(acc[mt][nt], ah[mt], bl[nt]);
                    mma_bf16(acc[mt][nt], al[mt], bh[nt]);
                }
        }
        __syncthreads();
    }

    const int lr = lane >> 2;
    const int lc = (lane & 3) * 2;
    const int bn = blockIdx.x * 128;

    #pragma unroll
    for (int mt = 0; mt < 4; mt++) {
        int r0 = bm + wm + mt * 16 + lr;
        #pragma unroll
        for (int nt = 0; nt < 4; nt++) {
            int col = bn + wn + nt * 8 + lc;
            float b0v = bias[col], b1v = bias[col + 1];
            float* a = acc[mt][nt];
            if (mode == 0) {
                *(float2*)&Cf[(size_t)r0 * 512 + col] = make_float2(a[0] + b0v, a[1] + b1v);
                *(float2*)&Cf[(size_t)(r0 + 8) * 512 + col] = make_float2(a[2] + b0v, a[3] + b1v);
            } else if (mode == 1) {
                int h_ = col >> 6, d_ = col & 63;
                #pragma unroll
                for (int rr = 0; rr < 2; rr++) {
                    int r = r0 + rr * 8;
                    int b_ = r >> 10, l_ = r & 1023;
                    *(float2*)&Cf[(((size_t)(b_ * HH + h_)) * LL + l_) * DD + d_] =
                        make_float2(a[rr * 2] + b0v, a[rr * 2 + 1] + b1v);
                }
            } else if (mode == 2) {
                int h_ = col >> 6, d_ = col & 63;
                #pragma unroll
                for (int rr = 0; rr < 2; rr++) {
                    int r = r0 + rr * 8;
                    int b_ = r >> 10, l_ = r & 1023;
                    size_t base = (((size_t)(b_ * HH + h_)) * DD + d_) * LL + l_;
                    Cf[base]      = a[rr * 2]     + b0v;
                    Cf[base + LL] = a[rr * 2 + 1] + b1v;
                }
            } else {   // mode 3: V as fp16 hi/lo packed (b,h,l,d/2)
                int h_ = col >> 6, d_ = col & 63;
                #pragma unroll
                for (int rr = 0; rr < 2; rr++) {
                    int r = r0 + rr * 8;
                    int b_ = r >> 10, l_ = r & 1023;
                    float v0 = a[rr * 2] + b0v, v1 = a[rr * 2 + 1] + b1v;
                    uint32_t hv = packhf(v0, v1);
                    __half2 hh = *(__half2*)&hv;
                    float2 f = __half22float2(hh);
                    uint32_t lv = packhf(v0 - f.x, v1 - f.y);
                    size_t idx = (((size_t)(b_ * HH + h_)) * LL + l_) * 32 + (d_ >> 1);
                    Ch[idx] = hv; Cl[idx] = lv;
                }
            }
        }
    }
}

// ===========================================================================
// Flash attention on HMMA. No-max softmax (scores bounded), deferred l-reduce.
// V arrives pre-split fp16; output written pre-split bf16.
// ===========================================================================
#define QST 72
#define KST 136
#define VST 72

__global__ void __launch_bounds__(256, 1) attn_mma(
    const float* __restrict__ q, const float* __restrict__ kT,
    const uint32_t* __restrict__ vh, const uint32_t* __restrict__ vl,
    const float* __restrict__ toep,
    uint32_t* __restrict__ xh, uint32_t* __restrict__ xl)
{
    extern __shared__ char smc[];
    uint32_t* QhU = (uint32_t*)smc;                        // 128*36
    uint32_t* QlU = QhU + 128 * QST / 2;
    uint32_t* KhU = QlU + 128 * QST / 2;                   // 64*68
    uint32_t* KlU = KhU + 64 * KST / 2;
    uint32_t* VhU = KlU + 64 * KST / 2;                    // 128*36
    uint32_t* VlU = VhU + 128 * VST / 2;
    float*    Tp  = (float*)(VlU + 128 * VST / 2);         // 4096

    const int t    = threadIdx.x;
    const int warp = t >> 5;
    const int lane = t & 31;
    const int lr   = lane >> 2;
    const int lc   = (lane & 3) * 2;
    const int qt   = blockIdx.x;
    const int h    = blockIdx.y;
    const int b    = blockIdx.z;
    const int bh   = b * HH + h;

    const float*    qb  = q  + (size_t)bh * LL * DD + (size_t)qt * 128 * DD;
    const float*    kb  = kT + (size_t)bh * DD * LL;
    const uint32_t* vhb = vh + (size_t)bh * LL * 32;
    const uint32_t* vlb = vl + (size_t)bh * LL * 32;

    // Q tile -> bf16 hi/lo smem; toeplitz row -> smem
    #pragma unroll
    for (int ch = 0; ch < 8; ch++) {
        int fi = ch * 256 + t;
        int row = fi >> 4, dc = (fi & 15) * 4;
        float4 vv = *(const float4*)(qb + (size_t)row * 64 + dc);
        uint32_t h0 = packbf(vv.x, vv.y), h1 = packbf(vv.z, vv.w);
        float rx = vv.x - __uint_as_float(h0 << 16);
        float ry = vv.y - __uint_as_float(h0 & 0xFFFF0000u);
        float rz = vv.z - __uint_as_float(h1 << 16);
        float rw = vv.w - __uint_as_float(h1 & 0xFFFF0000u);
        int o = row * (QST / 2) + (dc >> 1);
        QhU[o] = h0; QhU[o + 1] = h1;
        QlU[o] = packbf(rx, ry); QlU[o + 1] = packbf(rz, rw);
    }
    {
        const float4* tg = (const float4*)(toep + (size_t)h * 4096);
        #pragma unroll
        for (int ch = 0; ch < 4; ch++) {
            int fi = ch * 256 + t;
            *(float4*)&Tp[fi * 4] = tg[fi];
        }
    }

    int qg0 = qt * 128 + warp * 16 + lr;
    int qg1 = qg0 + 8;
    const int qo0 = ((qg0 >> 5) << 6) + (qg0 & 31) + 2080;
    const int qo1 = ((qg1 >> 5) << 6) + (qg1 & 31) + 2080;

    float l0 = 0.f, l1 = 0.f;
    float O[8][4];
    #pragma unroll
    for (int nf = 0; nf < 8; nf++)
        #pragma unroll
        for (int i = 0; i < 4; i++) O[nf][i] = 0.f;

    const float scale = 0.125f;

    for (int kt = 0; kt < 8; kt++) {
        // K chunk: [64 d][128 keys] fp32 -> bf16 hi/lo
        #pragma unroll
        for (int ch = 0; ch < 8; ch++) {
            int fi = ch * 256 + t;
            int d = fi >> 5, kc = (fi & 31) * 4;
            float4 vv = *(const float4*)(kb + (size_t)d * LL + kt * 128 + kc);
            uint32_t h0 = packbf(vv.x, vv.y), h1 = packbf(vv.z, vv.w);
            float rx = vv.x - __uint_as_float(h0 << 16);
            float ry = vv.y - __uint_as_float(h0 & 0xFFFF0000u);
            float rz = vv.z - __uint_as_float(h1 << 16);
            float rw = vv.w - __uint_as_float(h1 & 0xFFFF0000u);
            int o = d * (KST / 2) + (kc >> 1);
            KhU[o] = h0; KhU[o + 1] = h1;
            KlU[o] = packbf(rx, ry); KlU[o + 1] = packbf(rz, rw);
        }
        // V chunk: direct copy of pre-split fp16 (4 uint4 per thread per buf)
        #pragma unroll
        for (int j = 0; j < 4; j++) {
            int id = t + 256 * j;
            int key = id >> 3, seg = (id & 7) * 4;
            int so = key * (VST / 2) + seg;
            size_t g = (size_t)(kt * 128 + key) * 32 + seg;
            *(uint4*)&VhU[so] = *(const uint4*)(vhb + g);
            *(uint4*)&VlU[so] = *(const uint4*)(vlb + g);
        }
        __syncthreads();

        // ---- S = Q K^T (split bf16, 3 passes) ----
        float S[16][4];
        #pragma unroll
        for (int nf = 0; nf < 16; nf++)
            #pragma unroll
            for (int i = 0; i < 4; i++) S[nf][i] = 0.f;

        #pragma unroll
        for (int ks = 0; ks < 4; ks++) {
            uint32_t ah[4], al[4];
            int arow = warp * 16 + (lane & 15);
            int acol = ks * 16 + ((lane >> 4) << 3);
            ldsm4(ah, s2u((const char*)QhU + (arow * QST + acol) * 2));
            ldsm4(al, s2u((const char*)QlU + (arow * QST + acol) * 2));
            int brow = ks * 16 + (lane & 15);
            int bcol = (lane >> 4) << 3;
            #pragma unroll
            for (int nf2 = 0; nf2 < 8; nf2++) {
                uint32_t bhv[4], blv[4];
                int boff = (brow * KST + nf2 * 16 + bcol) * 2;
                ldsm4t(bhv, s2u((const char*)KhU + boff));
                ldsm4t(blv, s2u((const char*)KlU + boff));
                mma_bf16(S[nf2 * 2],     ah, bhv);
                mma_bf16(S[nf2 * 2],     ah, blv);
                mma_bf16(S[nf2 * 2],     al, bhv);
                mma_bf16(S[nf2 * 2 + 1], ah, bhv + 2);
                mma_bf16(S[nf2 * 2 + 1], ah, blv + 2);
                mma_bf16(S[nf2 * 2 + 1], al, bhv + 2);
            }
        }

        // ---- scale + bias + exp (no max subtraction; S bounded) ----
        float sum0 = 0.f, sum1 = 0.f;
        uint32_t ph[16][2];
        #pragma unroll
        for (int nf = 0; nf < 16; nf++) {
            int kg0 = kt * 128 + nf * 8 + lc;
            int ko0 = ((kg0 >> 5) << 6) + (kg0 & 31);
            int kg1 = kg0 + 1;
            int ko1 = ((kg1 >> 5) << 6) + (kg1 & 31);
            float e0 = __expf(S[nf][0] * scale + Tp[qo0 - ko0]);
            float e1 = __expf(S[nf][1] * scale + Tp[qo0 - ko1]);
            float e2 = __expf(S[nf][2] * scale + Tp[qo1 - ko0]);
            float e3 = __expf(S[nf][3] * scale + Tp[qo1 - ko1]);
            sum0 += e0 + e1;
            sum1 += e2 + e3;
            ph[nf][0] = packhf(e0, e1);
            ph[nf][1] = packhf(e2, e3);
        }
        l0 += sum0;
        l1 += sum1;

        // ---- O += P V (fp16, V split 2 passes) ----
        #pragma unroll
        for (int ks = 0; ks < 8; ks++) {
            uint32_t pa[4] = { ph[ks * 2][0], ph[ks * 2][1],
                               ph[ks * 2 + 1][0], ph[ks * 2 + 1][1] };
            int brow = ks * 16 + (lane & 15);
            int bcol = (lane >> 4) << 3;
            #pragma unroll
            for (int nf2 = 0; nf2 < 4; nf2++) {
                uint32_t bhv[4], blv[4];
                int boff = (brow * VST + nf2 * 16 + bcol) * 2;
                ldsm4t(bhv, s2u((const char*)VhU + boff));
                ldsm4t(blv, s2u((const char*)VlU + boff));
                mma_f16(O[nf2 * 2],     pa, bhv);
                mma_f16(O[nf2 * 2],     pa, blv);
                mma_f16(O[nf2 * 2 + 1], pa, bhv + 2);
                mma_f16(O[nf2 * 2 + 1], pa, blv + 2);
            }
        }
        __syncthreads();
    }

    // deferred l reduction across the 4 lanes of each row-quad
    l0 += __shfl_xor_sync(0xffffffffu, l0, 1);
    l0 += __shfl_xor_sync(0xffffffffu, l0, 2);
    l1 += __shfl_xor_sync(0xffffffffu, l1, 1);
    l1 += __shfl_xor_sync(0xffffffffu, l1, 2);

    float inv0 = 1.0f / l0, inv1 = 1.0f / l1;
    int row0 = b * LL + qt * 128 + warp * 16 + lr;
    #pragma unroll
    for (int nf = 0; nf < 8; nf++) {
        int colu = (h * 64 + nf * 8 + lc) >> 1;
        float v0 = O[nf][0] * inv0, v1 = O[nf][1] * inv0;
        uint32_t hv = packbf(v0, v1);
        uint32_t lv = packbf(v0 - __uint_as_float(hv << 16),
                             v1 - __uint_as_float(hv & 0xFFFF0000u));
        xh[(size_t)row0 * 256 + colu] = hv;
        xl[(size_t)row0 * 256 + colu] = lv;
        float v2 = O[nf][2] * inv1, v3 = O[nf][3] * inv1;
        uint32_t hv2 = packbf(v2, v3);
        uint32_t lv2 = packbf(v2 - __uint_as_float(hv2 << 16),
                              v3 - __uint_as_float(hv2 & 0xFFFF0000u));
        xh[(size_t)(row0 + 8) * 256 + colu] = hv2;
        xl[(size_t)(row0 + 8) * 256 + colu] = lv2;
    }
}

// ===========================================================================
extern "C" void kernel_launch(void* const* d_in, const int* in_sizes, int n_in,
                              void* d_out, int out_size)
{
    const float* inq  = (const float*)d_in[0];
    const float* inkv = (const float*)d_in[1];
    const float* Wq   = (const float*)d_in[2];
    const float* bq   = (const float*)d_in[3];
    const float* Wk   = (const float*)d_in[4];
    const float* bk   = (const float*)d_in[5];
    const float* Wv   = (const float*)d_in[6];
    const float* bv   = (const float*)d_in[7];
    const float* Wo   = (const float*)d_in[8];
    const float* bo   = (const float*)d_in[9];
    const float* toep = (const float*)d_in[10];
    float* out = (float*)d_out;

    float *pq, *pkT;
    uint32_t *piqh, *piql, *pikh, *pikl, *pwh, *pwl, *pvh, *pvl, *pxh, *pxl;
    cudaGetSymbolAddress((void**)&pq,   g_q);
    cudaGetSymbolAddress((void**)&pkT,  g_kT);
    cudaGetSymbolAddress((void**)&piqh, g_iqh);
    cudaGetSymbolAddress((void**)&piql, g_iql);
    cudaGetSymbolAddress((void**)&pikh, g_ikh);
    cudaGetSymbolAddress((void**)&pikl, g_ikl);
    cudaGetSymbolAddress((void**)&pwh,  g_wh);
    cudaGetSymbolAddress((void**)&pwl,  g_wl);
    cudaGetSymbolAddress((void**)&pvh,  g_vh);
    cudaGetSymbolAddress((void**)&pvl,  g_vl);
    cudaGetSymbolAddress((void**)&pxh,  g_xh);
    cudaGetSymbolAddress((void**)&pxl,  g_xl);

    const int WSZ = 512 * 256;   // uint32 per weight buffer

    // conversions
    conv_split<<<8192, 256>>>((const float4*)inq,  piqh, piql, 2097152);
    conv_split<<<8192, 256>>>((const float4*)inkv, pikh, pikl, 2097152);
    conv_split<<<256, 256>>>((const float4*)Wq, pwh + 0 * WSZ, pwl + 0 * WSZ, 65536);
    conv_split<<<256, 256>>>((const float4*)Wk, pwh + 1 * WSZ, pwl + 1 * WSZ, 65536);
    conv_split<<<256, 256>>>((const float4*)Wv, pwh + 2 * WSZ, pwl + 2 * WSZ, 65536);
    conv_split<<<256, 256>>>((const float4*)Wo, pwh + 3 * WSZ, pwl + 3 * WSZ, 65536);

    cudaFuncSetAttribute(gemm_bf, cudaFuncAttributeMaxDynamicSharedMemorySize, GB_SMEM);
    dim3 gg(4, 128);

    gemm_bf<<<gg, 256, GB_SMEM>>>(piqh, piql, pwh + 0 * WSZ, pwl + 0 * WSZ, bq, pq,  0, 0, 1);
    gemm_bf<<<gg, 256, GB_SMEM>>>(pikh, pikl, pwh + 1 * WSZ, pwl + 1 * WSZ, bk, pkT, 0, 0, 2);
    gemm_bf<<<gg, 256, GB_SMEM>>>(pikh, pikl, pwh + 2 * WSZ, pwl + 2 * WSZ, bv, 0, pvh, pvl, 3);

    int smem = 2 * (128 * QST * 2) + 2 * (64 * KST * 2) + 2 * (128 * VST * 2) + 4096 * 4;
    cudaFuncSetAttribute(attn_mma, cudaFuncAttributeMaxDynamicSharedMemorySize, smem);
    attn_mma<<<dim3(8, HH, BB), 256, smem>>>(pq, pkT, pvh, pvl, toep, pxh, pxl);

    gemm_bf<<<gg, 256, GB_SMEM>>>(pxh, pxl, pwh + 3 * WSZ, pwl + 3 * WSZ, bo, out, 0, 0, 0);
}

// round 10
// speedup vs baseline: 1.1495x; 1.1495x over previous
#include <cuda_runtime.h>
#include <cuda_bf16.h>
#include <cuda_fp16.h>
#include <cstdint>

#define BB 16
#define LL 1024
#define FF 512
#define HH 8
#define DD 64

__device__ float g_q[BB*HH*LL*DD];
__device__ float g_kT[BB*HH*DD*LL];   // K transposed: [b][h][d][l]
__device__ float g_v[BB*HH*LL*DD];
__device__ float g_x[BB*LL*HH*DD];

// ===========================================================================
// mma.sync helpers
// ===========================================================================
__device__ __forceinline__ uint32_t s2u(const void* p) {
    return (uint32_t)__cvta_generic_to_shared(p);
}
__device__ __forceinline__ void ldsm4(uint32_t* r, uint32_t a) {
    asm volatile("ldmatrix.sync.aligned.m8n8.x4.shared.b16 {%0,%1,%2,%3}, [%4];"
                 : "=r"(r[0]), "=r"(r[1]), "=r"(r[2]), "=r"(r[3]) : "r"(a));
}
__device__ __forceinline__ void ldsm4t(uint32_t* r, uint32_t a) {
    asm volatile("ldmatrix.sync.aligned.m8n8.x4.trans.shared.b16 {%0,%1,%2,%3}, [%4];"
                 : "=r"(r[0]), "=r"(r[1]), "=r"(r[2]), "=r"(r[3]) : "r"(a));
}
__device__ __forceinline__ void mma_bf16(float* c, const uint32_t* a, const uint32_t* b) {
    asm volatile(
        "mma.sync.aligned.m16n8k16.row.col.f32.bf16.bf16.f32 "
        "{%0,%1,%2,%3}, {%4,%5,%6,%7}, {%8,%9}, {%0,%1,%2,%3};"
        : "+f"(c[0]), "+f"(c[1]), "+f"(c[2]), "+f"(c[3])
        : "r"(a[0]), "r"(a[1]), "r"(a[2]), "r"(a[3]), "r"(b[0]), "r"(b[1]));
}
__device__ __forceinline__ void mma_f16(float* c, const uint32_t* a, const uint32_t* b) {
    asm volatile(
        "mma.sync.aligned.m16n8k16.row.col.f32.f16.f16.f32 "
        "{%0,%1,%2,%3}, {%4,%5,%6,%7}, {%8,%9}, {%0,%1,%2,%3};"
        : "+f"(c[0]), "+f"(c[1]), "+f"(c[2]), "+f"(c[3])
        : "r"(a[0]), "r"(a[1]), "r"(a[2]), "r"(a[3]), "r"(b[0]), "r"(b[1]));
}
__device__ __forceinline__ uint32_t packbf(float a, float b) {
    uint32_t r;
    asm("cvt.rn.bf16x2.f32 %0, %1, %2;" : "=r"(r) : "f"(b), "f"(a));
    return r;
}
__device__ __forceinline__ uint32_t packhf(float a, float b) {
    __half2 h = __floats2half2_rn(a, b);
    return *(uint32_t*)&h;
}

// ===========================================================================
// Tensor-core split-bf16 GEMM (R6 structure + occupancy hint): C = A @ W + bias
// ===========================================================================
#define SA 40
#define SB 136

__global__ void __launch_bounds__(256, 2) gemm_mma(
    const float* __restrict__ A, const float* __restrict__ W,
    const float* __restrict__ bias, float* __restrict__ C, int mode)
{
    __shared__ uint32_t AhU[128 * SA / 2], AlU[128 * SA / 2];
    __shared__ uint32_t BhU[32 * SB / 2],  BlU[32 * SB / 2];

    const int t    = threadIdx.x;
    const int warp = t >> 5;
    const int lane = t & 31;
    const int bm   = blockIdx.y * 128;
    const int bn   = blockIdx.x * 128;
    const int wm   = (warp >> 2) * 64;
    const int wn   = (warp & 3) * 32;

    float acc[4][4][4];
    #pragma unroll
    for (int mt = 0; mt < 4; mt++)
        #pragma unroll
        for (int nt = 0; nt < 4; nt++)
            #pragma unroll
            for (int i = 0; i < 4; i++) acc[mt][nt][i] = 0.f;

    for (int c = 0; c < 16; c++) {
        const int k0 = c * 32;
        __syncthreads();
        #pragma unroll
        for (int ch = 0; ch < 4; ch++) {
            int fi = ch * 256 + t;
            int m  = fi >> 3;
            int kc = (fi & 7) * 4;
            float4 v = *(const float4*)(A + (size_t)(bm + m) * 512 + k0 + kc);
            uint32_t h0 = packbf(v.x, v.y), h1 = packbf(v.z, v.w);
            float rx = v.x - __uint_as_float(h0 << 16);
            float ry = v.y - __uint_as_float(h0 & 0xFFFF0000u);
            float rz = v.z - __uint_as_float(h1 << 16);
            float rw = v.w - __uint_as_float(h1 & 0xFFFF0000u);
            int o = m * (SA / 2) + (kc >> 1);
            AhU[o] = h0; AhU[o + 1] = h1;
            AlU[o] = packbf(rx, ry); AlU[o + 1] = packbf(rz, rw);
        }
        #pragma unroll
        for (int ch = 0; ch < 4; ch++) {
            int fi = ch * 256 + t;
            int kr = fi >> 5;
            int nc = (fi & 31) * 4;
            float4 v = *(const float4*)(W + (size_t)(k0 + kr) * 512 + bn + nc);
            uint32_t h0 = packbf(v.x, v.y), h1 = packbf(v.z, v.w);
            float rx = v.x - __uint_as_float(h0 << 16);
            float ry = v.y - __uint_as_float(h0 & 0xFFFF0000u);
            float rz = v.z - __uint_as_float(h1 << 16);
            float rw = v.w - __uint_as_float(h1 & 0xFFFF0000u);
            int o = kr * (SB / 2) + (nc >> 1);
            BhU[o] = h0; BhU[o + 1] = h1;
            BlU[o] = packbf(rx, ry); BlU[o + 1] = packbf(rz, rw);
        }
        __syncthreads();

        #pragma unroll
        for (int ks = 0; ks < 2; ks++) {
            const int kk = ks * 16;
            uint32_t ah[4][4], al[4][4];
            {
                int arow = (lane & 15);
                int acol = kk + ((lane >> 4) << 3);
                #pragma unroll
                for (int mt = 0; mt < 4; mt++) {
                    int boff = ((wm + mt * 16 + arow) * SA + acol) * 2;
                    ldsm4(ah[mt], s2u((const char*)AhU + boff));
                    ldsm4(al[mt], s2u((const char*)AlU + boff));
                }
            }
            uint32_t bh[4][2], bl[4][2];
            {
                int brow = kk + (lane & 15);
                int bcol = ((lane >> 4) << 3);
                #pragma unroll
                for (int ntp = 0; ntp < 2; ntp++) {
                    int boff = (brow * SB + wn + ntp * 16 + bcol) * 2;
                    uint32_t tmp[4];
                    ldsm4t(tmp, s2u((const char*)BhU + boff));
                    bh[ntp * 2][0] = tmp[0]; bh[ntp * 2][1] = tmp[1];
                    bh[ntp * 2 + 1][0] = tmp[2]; bh[ntp * 2 + 1][1] = tmp[3];
                    ldsm4t(tmp, s2u((const char*)BlU + boff));
                    bl[ntp * 2][0] = tmp[0]; bl[ntp * 2][1] = tmp[1];
                    bl[ntp * 2 + 1][0] = tmp[2]; bl[ntp * 2 + 1][1] = tmp[3];
                }
            }
            #pragma unroll
            for (int mt = 0; mt < 4; mt++)
                #pragma unroll
                for (int nt = 0; nt < 4; nt++) {
                    mma_bf16(acc[mt][nt], ah[mt], bh[nt]);
                    mma_bf16(acc[mt][nt], ah[mt], bl[nt]);
                    mma_bf16(acc[mt][nt], al[mt], bh[nt]);
                }
        }
    }

    const int lr = lane >> 2;
    const int lc = (lane & 3) * 2;

    #pragma unroll
    for (int mt = 0; mt < 4; mt++) {
        int r0 = bm + wm + mt * 16 + lr;
        #pragma unroll
        for (int nt = 0; nt < 4; nt++) {
            int col = bn + wn + nt * 8 + lc;
            float b0v = bias[col], b1v = bias[col + 1];
            float* a = acc[mt][nt];
            if (mode == 0) {
                *(float2*)&C[(size_t)r0 * 512 + col] = make_float2(a[0] + b0v, a[1] + b1v);
                *(float2*)&C[(size_t)(r0 + 8) * 512 + col] = make_float2(a[2] + b0v, a[3] + b1v);
            } else if (mode == 1) {
                int h_ = col >> 6, d_ = col & 63;
                #pragma unroll
                for (int rr = 0; rr < 2; rr++) {
                    int r = r0 + rr * 8;
                    int b_ = r >> 10, l_ = r & 1023;
                    *(float2*)&C[(((size_t)(b_ * HH + h_)) * LL + l_) * DD + d_] =
                        make_float2(a[rr * 2] + b0v, a[rr * 2 + 1] + b1v);
                }
            } else {
                int h_ = col >> 6, d_ = col & 63;
                #pragma unroll
                for (int rr = 0; rr < 2; rr++) {
                    int r = r0 + rr * 8;
                    int b_ = r >> 10, l_ = r & 1023;
                    size_t base = (((size_t)(b_ * HH + h_)) * DD + d_) * LL + l_;
                    C[base]      = a[rr * 2]     + b0v;
                    C[base + LL] = a[rr * 2 + 1] + b1v;
                }
            }
        }
    }
}

// ===========================================================================
// Flash attention on HMMA (R7 structure). No-max softmax (scores bounded),
// deferred l-reduce. QK: split-bf16 3-pass. PV: P fp16, V fp16 hi/lo 2-pass.
// ===========================================================================
#define QST 72
#define KST 136
#define VST 72

__global__ void __launch_bounds__(256, 1) attn_mma(
    const float* __restrict__ q, const float* __restrict__ kT,
    const float* __restrict__ v, const float* __restrict__ toep,
    float* __restrict__ x)
{
    extern __shared__ char smc[];
    uint32_t* QhU = (uint32_t*)smc;
    uint32_t* QlU = QhU + 128 * QST / 2;
    uint32_t* KhU = QlU + 128 * QST / 2;
    uint32_t* KlU = KhU + 64 * KST / 2;
    uint32_t* VhU = KlU + 64 * KST / 2;
    uint32_t* VlU = VhU + 128 * VST / 2;
    float*    Tp  = (float*)(VlU + 128 * VST / 2);

    const int t    = threadIdx.x;
    const int warp = t >> 5;
    const int lane = t & 31;
    const int lr   = lane >> 2;
    const int lc   = (lane & 3) * 2;
    const int qt   = blockIdx.x;
    const int h    = blockIdx.y;
    const int b    = blockIdx.z;
    const int bh   = b * HH + h;

    const float* qb = q  + (size_t)bh * LL * DD + (size_t)qt * 128 * DD;
    const float* kb = kT + (size_t)bh * DD * LL;
    const float* vb = v  + (size_t)bh * LL * DD;

    #pragma unroll
    for (int ch = 0; ch < 8; ch++) {
        int fi = ch * 256 + t;
        int row = fi >> 4, dc = (fi & 15) * 4;
        float4 vv = *(const float4*)(qb + (size_t)row * 64 + dc);
        uint32_t h0 = packbf(vv.x, vv.y), h1 = packbf(vv.z, vv.w);
        float rx = vv.x - __uint_as_float(h0 << 16);
        float ry = vv.y - __uint_as_float(h0 & 0xFFFF0000u);
        float rz = vv.z - __uint_as_float(h1 << 16);
        float rw = vv.w - __uint_as_float(h1 & 0xFFFF0000u);
        int o = row * (QST / 2) + (dc >> 1);
        QhU[o] = h0; QhU[o + 1] = h1;
        QlU[o] = packbf(rx, ry); QlU[o + 1] = packbf(rz, rw);
    }
    {
        const float4* tg = (const float4*)(toep + (size_t)h * 4096);
        #pragma unroll
        for (int ch = 0; ch < 4; ch++) {
            int fi = ch * 256 + t;
            *(float4*)&Tp[fi * 4] = tg[fi];
        }
    }

    int qg0 = qt * 128 + warp * 16 + lr;
    int qg1 = qg0 + 8;
    const int qo0 = ((qg0 >> 5) << 6) + (qg0 & 31) + 2080;
    const int qo1 = ((qg1 >> 5) << 6) + (qg1 & 31) + 2080;

    float l0 = 0.f, l1 = 0.f;
    float O[8][4];
    #pragma unroll
    for (int nf = 0; nf < 8; nf++)
        #pragma unroll
        for (int i = 0; i < 4; i++) O[nf][i] = 0.f;

    const float scale = 0.125f;

    for (int kt = 0; kt < 8; kt++) {
        #pragma unroll
        for (int ch = 0; ch < 8; ch++) {
            int fi = ch * 256 + t;
            int d = fi >> 5, kc = (fi & 31) * 4;
            float4 vv = *(const float4*)(kb + (size_t)d * LL + kt * 128 + kc);
            uint32_t h0 = packbf(vv.x, vv.y), h1 = packbf(vv.z, vv.w);
            float rx = vv.x - __uint_as_float(h0 << 16);
            float ry = vv.y - __uint_as_float(h0 & 0xFFFF0000u);
            float rz = vv.z - __uint_as_float(h1 << 16);
            float rw = vv.w - __uint_as_float(h1 & 0xFFFF0000u);
            int o = d * (KST / 2) + (kc >> 1);
            KhU[o] = h0; KhU[o + 1] = h1;
            KlU[o] = packbf(rx, ry); KlU[o + 1] = packbf(rz, rw);
        }
        #pragma unroll
        for (int ch = 0; ch < 8; ch++) {
            int fi = ch * 256 + t;
            int key = fi >> 4, dc = (fi & 15) * 4;
            float4 vv = *(const float4*)(vb + (size_t)(kt * 128 + key) * 64 + dc);
            uint32_t h0 = packhf(vv.x, vv.y), h1 = packhf(vv.z, vv.w);
            __half2 hh0 = *(__half2*)&h0, hh1 = *(__half2*)&h1;
            float2 f0 = __half22float2(hh0), f1 = __half22float2(hh1);
            int o = key * (VST / 2) + (dc >> 1);
            VhU[o] = h0; VhU[o + 1] = h1;
            VlU[o] = packhf(vv.x - f0.x, vv.y - f0.y);
            VlU[o + 1] = packhf(vv.z - f1.x, vv.w - f1.y);
        }
        __syncthreads();

        // ---- S = Q K^T (split bf16, 3 passes) ----
        float S[16][4];
        #pragma unroll
        for (int nf = 0; nf < 16; nf++)
            #pragma unroll
            for (int i = 0; i < 4; i++) S[nf][i] = 0.f;

        #pragma unroll
        for (int ks = 0; ks < 4; ks++) {
            uint32_t ah[4], al[4];
            int arow = warp * 16 + (lane & 15);
            int acol = ks * 16 + ((lane >> 4) << 3);
            ldsm4(ah, s2u((const char*)QhU + (arow * QST + acol) * 2));
            ldsm4(al, s2u((const char*)QlU + (arow * QST + acol) * 2));
            int brow = ks * 16 + (lane & 15);
            int bcol = (lane >> 4) << 3;
            #pragma unroll
            for (int nf2 = 0; nf2 < 8; nf2++) {
                uint32_t bhv[4], blv[4];
                int boff = (brow * KST + nf2 * 16 + bcol) * 2;
                ldsm4t(bhv, s2u((const char*)KhU + boff));
                ldsm4t(blv, s2u((const char*)KlU + boff));
                mma_bf16(S[nf2 * 2],     ah, bhv);
                mma_bf16(S[nf2 * 2],     ah, blv);
                mma_bf16(S[nf2 * 2],     al, bhv);
                mma_bf16(S[nf2 * 2 + 1], ah, bhv + 2);
                mma_bf16(S[nf2 * 2 + 1], ah, blv + 2);
                mma_bf16(S[nf2 * 2 + 1], al, bhv + 2);
            }
        }

        // ---- scale + bias + exp (no max subtraction; scores bounded) ----
        uint32_t ph[16][2];
        float sum0 = 0.f, sum1 = 0.f;
        #pragma unroll
        for (int nf = 0; nf < 16; nf++) {
            int kg0 = kt * 128 + nf * 8 + lc;
            int ko0 = ((kg0 >> 5) << 6) + (kg0 & 31);
            int kg1 = kg0 + 1;
            int ko1 = ((kg1 >> 5) << 6) + (kg1 & 31);
            float e0 = __expf(S[nf][0] * scale + Tp[qo0 - ko0]);
            float e1 = __expf(S[nf][1] * scale + Tp[qo0 - ko1]);
            float e2 = __expf(S[nf][2] * scale + Tp[qo1 - ko0]);
            float e3 = __expf(S[nf][3] * scale + Tp[qo1 - ko1]);
            sum0 += e0 + e1;
            sum1 += e2 + e3;
            ph[nf][0] = packhf(e0, e1);
            ph[nf][1] = packhf(e2, e3);
        }
        l0 += sum0;
        l1 += sum1;

        // ---- O += P V (fp16, V split 2 passes) ----
        #pragma unroll
        for (int ks = 0; ks < 8; ks++) {
            uint32_t pa[4] = { ph[ks * 2][0], ph[ks * 2][1],
                               ph[ks * 2 + 1][0], ph[ks * 2 + 1][1] };
            int brow = ks * 16 + (lane & 15);
            int bcol = (lane >> 4) << 3;
            #pragma unroll
            for (int nf2 = 0; nf2 < 4; nf2++) {
                uint32_t bhv[4], blv[4];
                int boff = (brow * VST + nf2 * 16 + bcol) * 2;
                ldsm4t(bhv, s2u((const char*)VhU + boff));
                ldsm4t(blv, s2u((const char*)VlU + boff));
                mma_f16(O[nf2 * 2],     pa, bhv);
                mma_f16(O[nf2 * 2],     pa, blv);
                mma_f16(O[nf2 * 2 + 1], pa, bhv + 2);
                mma_f16(O[nf2 * 2 + 1], pa, blv + 2);
            }
        }
        __syncthreads();
    }

    // deferred l reduction across the 4 lanes sharing each row
    l0 += __shfl_xor_sync(0xffffffffu, l0, 1);
    l0 += __shfl_xor_sync(0xffffffffu, l0, 2);
    l1 += __shfl_xor_sync(0xffffffffu, l1, 1);
    l1 += __shfl_xor_sync(0xffffffffu, l1, 2);

    float inv0 = 1.0f / l0, inv1 = 1.0f / l1;
    int row0 = b * LL + qt * 128 + warp * 16 + lr;
    #pragma unroll
    for (int nf = 0; nf < 8; nf++) {
        int col = h * 64 + nf * 8 + lc;
        *(float2*)&x[(size_t)row0 * 512 + col] =
            make_float2(O[nf][0] * inv0, O[nf][1] * inv0);
        *(float2*)&x[(size_t)(row0 + 8) * 512 + col] =
            make_float2(O[nf][2] * inv1, O[nf][3] * inv1);
    }
}

// ===========================================================================
extern "C" void kernel_launch(void* const* d_in, const int* in_sizes, int n_in,
                              void* d_out, int out_size)
{
    const float* inq  = (const float*)d_in[0];
    const float* inkv = (const float*)d_in[1];
    const float* Wq   = (const float*)d_in[2];
    const float* bq   = (const float*)d_in[3];
    const float* Wk   = (const float*)d_in[4];
    const float* bk   = (const float*)d_in[5];
    const float* Wv   = (const float*)d_in[6];
    const float* bv   = (const float*)d_in[7];
    const float* Wo   = (const float*)d_in[8];
    const float* bo   = (const float*)d_in[9];
    const float* toep = (const float*)d_in[10];
    float* out = (float*)d_out;

    float *pq, *pkT, *pv, *px;
    cudaGetSymbolAddress((void**)&pq,  g_q);
    cudaGetSymbolAddress((void**)&pkT, g_kT);
    cudaGetSymbolAddress((void**)&pv,  g_v);
    cudaGetSymbolAddress((void**)&px,  g_x);

    dim3 gg(4, 128);

    gemm_mma<<<gg, 256>>>(inq,  Wq, bq, pq,  1);
    gemm_mma<<<gg, 256>>>(inkv, Wk, bk, pkT, 2);
    gemm_mma<<<gg, 256>>>(inkv, Wv, bv, pv,  1);

    int smem = 2 * (128 * QST * 2) + 2 * (64 * KST * 2) + 2 * (128 * VST * 2) + 4096 * 4;
    cudaFuncSetAttribute(attn_mma, cudaFuncAttributeMaxDynamicSharedMemorySize, smem);
    attn_mma<<<dim3(8, HH, BB), 256, smem>>>(pq, pkT, pv, toep, px);

    gemm_mma<<<gg, 256>>>(px, Wo, bo, out, 0);
}

// round 11
// speedup vs baseline: 1.3465x; 1.1714x over previous
#include <cuda_runtime.h>
#include <cuda_bf16.h>
#include <cuda_fp16.h>
#include <cstdint>

#define BB 16
#define LL 1024
#define FF 512
#define HH 8
#define DD 64

__device__ float g_q[BB*HH*LL*DD];
__device__ float g_kT[BB*HH*DD*LL];   // K transposed: [b][h][d][l]
__device__ float g_v[BB*HH*LL*DD];
__device__ float g_x[BB*LL*HH*DD];

// ===========================================================================
// mma.sync helpers
// ===========================================================================
__device__ __forceinline__ uint32_t s2u(const void* p) {
    return (uint32_t)__cvta_generic_to_shared(p);
}
__device__ __forceinline__ void ldsm4(uint32_t* r, uint32_t a) {
    asm volatile("ldmatrix.sync.aligned.m8n8.x4.shared.b16 {%0,%1,%2,%3}, [%4];"
                 : "=r"(r[0]), "=r"(r[1]), "=r"(r[2]), "=r"(r[3]) : "r"(a));
}
__device__ __forceinline__ void ldsm4t(uint32_t* r, uint32_t a) {
    asm volatile("ldmatrix.sync.aligned.m8n8.x4.trans.shared.b16 {%0,%1,%2,%3}, [%4];"
                 : "=r"(r[0]), "=r"(r[1]), "=r"(r[2]), "=r"(r[3]) : "r"(a));
}
__device__ __forceinline__ void mma_bf16(float* c, const uint32_t* a, const uint32_t* b) {
    asm volatile(
        "mma.sync.aligned.m16n8k16.row.col.f32.bf16.bf16.f32 "
        "{%0,%1,%2,%3}, {%4,%5,%6,%7}, {%8,%9}, {%0,%1,%2,%3};"
        : "+f"(c[0]), "+f"(c[1]), "+f"(c[2]), "+f"(c[3])
        : "r"(a[0]), "r"(a[1]), "r"(a[2]), "r"(a[3]), "r"(b[0]), "r"(b[1]));
}
__device__ __forceinline__ void mma_f16(float* c, const uint32_t* a, const uint32_t* b) {
    asm volatile(
        "mma.sync.aligned.m16n8k16.row.col.f32.f16.f16.f32 "
        "{%0,%1,%2,%3}, {%4,%5,%6,%7}, {%8,%9}, {%0,%1,%2,%3};"
        : "+f"(c[0]), "+f"(c[1]), "+f"(c[2]), "+f"(c[3])
        : "r"(a[0]), "r"(a[1]), "r"(a[2]), "r"(a[3]), "r"(b[0]), "r"(b[1]));
}
__device__ __forceinline__ uint32_t packbf(float a, float b) {
    uint32_t r;
    asm("cvt.rn.bf16x2.f32 %0, %1, %2;" : "=r"(r) : "f"(b), "f"(a));
    return r;
}
__device__ __forceinline__ uint32_t packhf(float a, float b) {
    __half2 h = __floats2half2_rn(a, b);
    return *(uint32_t*)&h;
}

// ===========================================================================
// Tensor-core split-bf16 GEMM (R6/R7 exact, validated): C = A @ W + bias
// ===========================================================================
#define SA 40
#define SB 136

__global__ void __launch_bounds__(256) gemm_mma(
    const float* __restrict__ A, const float* __restrict__ W,
    const float* __restrict__ bias, float* __restrict__ C, int mode)
{
    __shared__ uint32_t AhU[128 * SA / 2], AlU[128 * SA / 2];
    __shared__ uint32_t BhU[32 * SB / 2],  BlU[32 * SB / 2];

    const int t    = threadIdx.x;
    const int warp = t >> 5;
    const int lane = t & 31;
    const int bm   = blockIdx.y * 128;
    const int bn   = blockIdx.x * 128;
    const int wm   = (warp >> 2) * 64;
    const int wn   = (warp & 3) * 32;

    float acc[4][4][4];
    #pragma unroll
    for (int mt = 0; mt < 4; mt++)
        #pragma unroll
        for (int nt = 0; nt < 4; nt++)
            #pragma unroll
            for (int i = 0; i < 4; i++) acc[mt][nt][i] = 0.f;

    for (int c = 0; c < 16; c++) {
        const int k0 = c * 32;
        __syncthreads();
        #pragma unroll
        for (int ch = 0; ch < 4; ch++) {
            int fi = ch * 256 + t;
            int m  = fi >> 3;
            int kc = (fi & 7) * 4;
            float4 v = *(const float4*)(A + (size_t)(bm + m) * 512 + k0 + kc);
            uint32_t h0 = packbf(v.x, v.y), h1 = packbf(v.z, v.w);
            float rx = v.x - __uint_as_float(h0 << 16);
            float ry = v.y - __uint_as_float(h0 & 0xFFFF0000u);
            float rz = v.z - __uint_as_float(h1 << 16);
            float rw = v.w - __uint_as_float(h1 & 0xFFFF0000u);
            int o = m * (SA / 2) + (kc >> 1);
            AhU[o] = h0; AhU[o + 1] = h1;
            AlU[o] = packbf(rx, ry); AlU[o + 1] = packbf(rz, rw);
        }
        #pragma unroll
        for (int ch = 0; ch < 4; ch++) {
            int fi = ch * 256 + t;
            int kr = fi >> 5;
            int nc = (fi & 31) * 4;
            float4 v = *(const float4*)(W + (size_t)(k0 + kr) * 512 + bn + nc);
            uint32_t h0 = packbf(v.x, v.y), h1 = packbf(v.z, v.w);
            float rx = v.x - __uint_as_float(h0 << 16);
            float ry = v.y - __uint_as_float(h0 & 0xFFFF0000u);
            float rz = v.z - __uint_as_float(h1 << 16);
            float rw = v.w - __uint_as_float(h1 & 0xFFFF0000u);
            int o = kr * (SB / 2) + (nc >> 1);
            BhU[o] = h0; BhU[o + 1] = h1;
            BlU[o] = packbf(rx, ry); BlU[o + 1] = packbf(rz, rw);
        }
        __syncthreads();

        #pragma unroll
        for (int ks = 0; ks < 2; ks++) {
            const int kk = ks * 16;
            uint32_t ah[4][4], al[4][4];
            {
                int arow = (lane & 15);
                int acol = kk + ((lane >> 4) << 3);
                #pragma unroll
                for (int mt = 0; mt < 4; mt++) {
                    int boff = ((wm + mt * 16 + arow) * SA + acol) * 2;
                    ldsm4(ah[mt], s2u((const char*)AhU + boff));
                    ldsm4(al[mt], s2u((const char*)AlU + boff));
                }
            }
            uint32_t bh[4][2], bl[4][2];
            {
                int brow = kk + (lane & 15);
                int bcol = ((lane >> 4) << 3);
                #pragma unroll
                for (int ntp = 0; ntp < 2; ntp++) {
                    int boff = (brow * SB + wn + ntp * 16 + bcol) * 2;
                    uint32_t tmp[4];
                    ldsm4t(tmp, s2u((const char*)BhU + boff));
                    bh[ntp * 2][0] = tmp[0]; bh[ntp * 2][1] = tmp[1];
                    bh[ntp * 2 + 1][0] = tmp[2]; bh[ntp * 2 + 1][1] = tmp[3];
                    ldsm4t(tmp, s2u((const char*)BlU + boff));
                    bl[ntp * 2][0] = tmp[0]; bl[ntp * 2][1] = tmp[1];
                    bl[ntp * 2 + 1][0] = tmp[2]; bl[ntp * 2 + 1][1] = tmp[3];
                }
            }
            #pragma unroll
            for (int mt = 0; mt < 4; mt++)
                #pragma unroll
                for (int nt = 0; nt < 4; nt++) {
                    mma_bf16(acc[mt][nt], ah[mt], bh[nt]);
                    mma_bf16(acc[mt][nt], ah[mt], bl[nt]);
                    mma_bf16(acc[mt][nt], al[mt], bh[nt]);
                }
        }
    }

    const int lr = lane >> 2;
    const int lc = (lane & 3) * 2;

    #pragma unroll
    for (int mt = 0; mt < 4; mt++) {
        int r0 = bm + wm + mt * 16 + lr;
        #pragma unroll
        for (int nt = 0; nt < 4; nt++) {
            int col = bn + wn + nt * 8 + lc;
            float b0v = bias[col], b1v = bias[col + 1];
            float* a = acc[mt][nt];
            if (mode == 0) {
                *(float2*)&C[(size_t)r0 * 512 + col] = make_float2(a[0] + b0v, a[1] + b1v);
                *(float2*)&C[(size_t)(r0 + 8) * 512 + col] = make_float2(a[2] + b0v, a[3] + b1v);
            } else if (mode == 1) {
                int h_ = col >> 6, d_ = col & 63;
                #pragma unroll
                for (int rr = 0; rr < 2; rr++) {
                    int r = r0 + rr * 8;
                    int b_ = r >> 10, l_ = r & 1023;
                    *(float2*)&C[(((size_t)(b_ * HH + h_)) * LL + l_) * DD + d_] =
                        make_float2(a[rr * 2] + b0v, a[rr * 2 + 1] + b1v);
                }
            } else {
                int h_ = col >> 6, d_ = col & 63;
                #pragma unroll
                for (int rr = 0; rr < 2; rr++) {
                    int r = r0 + rr * 8;
                    int b_ = r >> 10, l_ = r & 1023;
                    size_t base = (((size_t)(b_ * HH + h_)) * DD + d_) * LL + l_;
                    C[base]      = a[rr * 2]     + b0v;
                    C[base + LL] = a[rr * 2 + 1] + b1v;
                }
            }
        }
    }
}

// ===========================================================================
// Flash attention on HMMA. QK: 2-pass (hi*hi + lo*hi; q_hi*k_lo dropped).
// PV: P fp16, V fp16 single pass. No-max softmax, deferred l-reduce.
// ===========================================================================
#define QST 72
#define KST 136
#define VST 72

__global__ void __launch_bounds__(256, 1) attn_mma(
    const float* __restrict__ q, const float* __restrict__ kT,
    const float* __restrict__ v, const float* __restrict__ toep,
    float* __restrict__ x)
{
    extern __shared__ char smc[];
    uint32_t* QhU = (uint32_t*)smc;
    uint32_t* QlU = QhU + 128 * QST / 2;
    uint32_t* KhU = QlU + 128 * QST / 2;
    uint32_t* VhU = KhU + 64 * KST / 2;
    float*    Tp  = (float*)(VhU + 128 * VST / 2);

    const int t    = threadIdx.x;
    const int warp = t >> 5;
    const int lane = t & 31;
    const int lr   = lane >> 2;
    const int lc   = (lane & 3) * 2;
    const int qt   = blockIdx.x;
    const int h    = blockIdx.y;
    const int b    = blockIdx.z;
    const int bh   = b * HH + h;

    const float* qb = q  + (size_t)bh * LL * DD + (size_t)qt * 128 * DD;
    const float* kb = kT + (size_t)bh * DD * LL;
    const float* vb = v  + (size_t)bh * LL * DD;

    #pragma unroll
    for (int ch = 0; ch < 8; ch++) {
        int fi = ch * 256 + t;
        int row = fi >> 4, dc = (fi & 15) * 4;
        float4 vv = *(const float4*)(qb + (size_t)row * 64 + dc);
        uint32_t h0 = packbf(vv.x, vv.y), h1 = packbf(vv.z, vv.w);
        float rx = vv.x - __uint_as_float(h0 << 16);
        float ry = vv.y - __uint_as_float(h0 & 0xFFFF0000u);
        float rz = vv.z - __uint_as_float(h1 << 16);
        float rw = vv.w - __uint_as_float(h1 & 0xFFFF0000u);
        int o = row * (QST / 2) + (dc >> 1);
        QhU[o] = h0; QhU[o + 1] = h1;
        QlU[o] = packbf(rx, ry); QlU[o + 1] = packbf(rz, rw);
    }
    {
        const float4* tg = (const float4*)(toep + (size_t)h * 4096);
        #pragma unroll
        for (int ch = 0; ch < 4; ch++) {
            int fi = ch * 256 + t;
            *(float4*)&Tp[fi * 4] = tg[fi];
        }
    }

    int qg0 = qt * 128 + warp * 16 + lr;
    int qg1 = qg0 + 8;
    const int qo0 = ((qg0 >> 5) << 6) + (qg0 & 31) + 2080;
    const int qo1 = ((qg1 >> 5) << 6) + (qg1 & 31) + 2080;

    float l0 = 0.f, l1 = 0.f;
    float O[8][4];
    #pragma unroll
    for (int nf = 0; nf < 8; nf++)
        #pragma unroll
        for (int i = 0; i < 4; i++) O[nf][i] = 0.f;

    const float scale = 0.125f;

    for (int kt = 0; kt < 8; kt++) {
        // K chunk: [64 d][128 keys] fp32 -> bf16 hi only
        #pragma unroll
        for (int ch = 0; ch < 8; ch++) {
            int fi = ch * 256 + t;
            int d = fi >> 5, kc = (fi & 31) * 4;
            float4 vv = *(const float4*)(kb + (size_t)d * LL + kt * 128 + kc);
            int o = d * (KST / 2) + (kc >> 1);
            KhU[o] = packbf(vv.x, vv.y);
            KhU[o + 1] = packbf(vv.z, vv.w);
        }
        // V chunk: [128 keys][64 d] fp32 -> fp16 hi only
        #pragma unroll
        for (int ch = 0; ch < 8; ch++) {
            int fi = ch * 256 + t;
            int key = fi >> 4, dc = (fi & 15) * 4;
            float4 vv = *(const float4*)(vb + (size_t)(kt * 128 + key) * 64 + dc);
            int o = key * (VST / 2) + (dc >> 1);
            VhU[o] = packhf(vv.x, vv.y);
            VhU[o + 1] = packhf(vv.z, vv.w);
        }
        __syncthreads();

        // ---- S = Q K^T (2 passes: q_hi*k + q_lo*k) ----
        float S[16][4];
        #pragma unroll
        for (int nf = 0; nf < 16; nf++)
            #pragma unroll
            for (int i = 0; i < 4; i++) S[nf][i] = 0.f;

        #pragma unroll
        for (int ks = 0; ks < 4; ks++) {
            uint32_t ah[4], al[4];
            int arow = warp * 16 + (lane & 15);
            int acol = ks * 16 + ((lane >> 4) << 3);
            ldsm4(ah, s2u((const char*)QhU + (arow * QST + acol) * 2));
            ldsm4(al, s2u((const char*)QlU + (arow * QST + acol) * 2));
            int brow = ks * 16 + (lane & 15);
            int bcol = (lane >> 4) << 3;
            #pragma unroll
            for (int nf2 = 0; nf2 < 8; nf2++) {
                uint32_t bhv[4];
                ldsm4t(bhv, s2u((const char*)KhU + (brow * KST + nf2 * 16 + bcol) * 2));
                mma_bf16(S[nf2 * 2],     ah, bhv);
                mma_bf16(S[nf2 * 2],     al, bhv);
                mma_bf16(S[nf2 * 2 + 1], ah, bhv + 2);
                mma_bf16(S[nf2 * 2 + 1], al, bhv + 2);
            }
        }

        // ---- scale + bias + exp (no max subtraction; scores bounded) ----
        uint32_t ph[16][2];
        float sum0 = 0.f, sum1 = 0.f;
        #pragma unroll
        for (int nf = 0; nf < 16; nf++) {
            int kg0 = kt * 128 + nf * 8 + lc;
            int ko0 = ((kg0 >> 5) << 6) + (kg0 & 31);
            int kg1 = kg0 + 1;
            int ko1 = ((kg1 >> 5) << 6) + (kg1 & 31);
            float e0 = __expf(S[nf][0] * scale + Tp[qo0 - ko0]);
            float e1 = __expf(S[nf][1] * scale + Tp[qo0 - ko1]);
            float e2 = __expf(S[nf][2] * scale + Tp[qo1 - ko0]);
            float e3 = __expf(S[nf][3] * scale + Tp[qo1 - ko1]);
            sum0 += e0 + e1;
            sum1 += e2 + e3;
            ph[nf][0] = packhf(e0, e1);
            ph[nf][1] = packhf(e2, e3);
        }
        l0 += sum0;
        l1 += sum1;

        // ---- O += P V (fp16, single pass) ----
        #pragma unroll
        for (int ks = 0; ks < 8; ks++) {
            uint32_t pa[4] = { ph[ks * 2][0], ph[ks * 2][1],
                               ph[ks * 2 + 1][0], ph[ks * 2 + 1][1] };
            int brow = ks * 16 + (lane & 15);
            int bcol = (lane >> 4) << 3;
            #pragma unroll
            for (int nf2 = 0; nf2 < 4; nf2++) {
                uint32_t bhv[4];
                ldsm4t(bhv, s2u((const char*)VhU + (brow * VST + nf2 * 16 + bcol) * 2));
                mma_f16(O[nf2 * 2],     pa, bhv);
                mma_f16(O[nf2 * 2 + 1], pa, bhv + 2);
            }
        }
        __syncthreads();
    }

    // deferred l reduction across the 4 lanes sharing each row
    l0 += __shfl_xor_sync(0xffffffffu, l0, 1);
    l0 += __shfl_xor_sync(0xffffffffu, l0, 2);
    l1 += __shfl_xor_sync(0xffffffffu, l1, 1);
    l1 += __shfl_xor_sync(0xffffffffu, l1, 2);

    float inv0 = 1.0f / l0, inv1 = 1.0f / l1;
    int row0 = b * LL + qt * 128 + warp * 16 + lr;
    #pragma unroll
    for (int nf = 0; nf < 8; nf++) {
        int col = h * 64 + nf * 8 + lc;
        *(float2*)&x[(size_t)row0 * 512 + col] =
            make_float2(O[nf][0] * inv0, O[nf][1] * inv0);
        *(float2*)&x[(size_t)(row0 + 8) * 512 + col] =
            make_float2(O[nf][2] * inv1, O[nf][3] * inv1);
    }
}

// ===========================================================================
extern "C" void kernel_launch(void* const* d_in, const int* in_sizes, int n_in,
                              void* d_out, int out_size)
{
    const float* inq  = (const float*)d_in[0];
    const float* inkv = (const float*)d_in[1];
    const float* Wq   = (const float*)d_in[2];
    const float* bq   = (const float*)d_in[3];
    const float* Wk   = (const float*)d_in[4];
    const float* bk   = (const float*)d_in[5];
    const float* Wv   = (const float*)d_in[6];
    const float* bv   = (const float*)d_in[7];
    const float* Wo   = (const float*)d_in[8];
    const float* bo   = (const float*)d_in[9];
    const float* toep = (const float*)d_in[10];
    float* out = (float*)d_out;

    float *pq, *pkT, *pv, *px;
    cudaGetSymbolAddress((void**)&pq,  g_q);
    cudaGetSymbolAddress((void**)&pkT, g_kT);
    cudaGetSymbolAddress((void**)&pv,  g_v);
    cudaGetSymbolAddress((void**)&px,  g_x);

    dim3 gg(4, 128);

    gemm_mma<<<gg, 256>>>(inq,  Wq, bq, pq,  1);
    gemm_mma<<<gg, 256>>>(inkv, Wk, bk, pkT, 2);
    gemm_mma<<<gg, 256>>>(inkv, Wv, bv, pv,  1);

    // smem: Qh/Ql 2*18432 + Kh 17408 + Vh 18432 + Tp 16384 = 89088 B
    int smem = 2 * (128 * QST * 2) + (64 * KST * 2) + (128 * VST * 2) + 4096 * 4;
    cudaFuncSetAttribute(attn_mma, cudaFuncAttributeMaxDynamicSharedMemorySize, smem);
    attn_mma<<<dim3(8, HH, BB), 256, smem>>>(pq, pkT, pv, toep, px);

    gemm_mma<<<gg, 256>>>(px, Wo, bo, out, 0);
}